// round 3
// baseline (speedup 1.0000x reference)
#include <cuda_runtime.h>

#define NN 100000
#define EMAX 3400000
#define F_IN 256
#define CH 16
#define CH2 8
#define NL 7

// ---------------- static scratch ----------------
__device__ __align__(128) float g_hs  [NN * CH];   // layer1 transform, pre-scaled by dinv[src]
__device__ __align__(128) float g_out1[NN * CH];   // layer1 conv output (post-scale)
__device__ __align__(128) float g_hs2 [NN * CH2];  // layer2 transform, pre-scaled (padded to 8)
__device__ float g_dinv[NN];
__device__ int   g_cnt    [NN];
__device__ int   g_rowptr [NN + 1];
__device__ int   g_cursor [NN];
__device__ int   g_partial[NN];
__device__ int   g_bsum   [1024];
__device__ int   g_perm   [EMAX];                  // src node of each edge, sorted by dst

// ---------------- CSR build: count / scan / permute ----------------
__global__ void k_zero() {
    int i = blockIdx.x * blockDim.x + threadIdx.x;
    if (i < NN) g_cnt[i] = 0;
}

__global__ void k_count(const int* __restrict__ dst, int E) {
    int i = blockIdx.x * blockDim.x + threadIdx.x;
    if (i < E) atomicAdd(&g_cnt[dst[i]], 1);
}

__global__ void __launch_bounds__(1024) k_scan1() {
    __shared__ int s[1024];
    int tid = threadIdx.x;
    int gid = blockIdx.x * 1024 + tid;
    int v = (gid < NN) ? g_cnt[gid] : 0;
    s[tid] = v;
    __syncthreads();
    #pragma unroll
    for (int off = 1; off < 1024; off <<= 1) {
        int t = (tid >= off) ? s[tid - off] : 0;
        __syncthreads();
        s[tid] += t;
        __syncthreads();
    }
    if (gid < NN) g_partial[gid] = s[tid] - v;      // exclusive within block
    if (tid == 1023) g_bsum[blockIdx.x] = s[1023];  // block total
}

__global__ void __launch_bounds__(1024) k_scan2(int nb) {
    __shared__ int s[1024];
    int tid = threadIdx.x;
    int v = (tid < nb) ? g_bsum[tid] : 0;
    s[tid] = v;
    __syncthreads();
    #pragma unroll
    for (int off = 1; off < 1024; off <<= 1) {
        int t = (tid >= off) ? s[tid - off] : 0;
        __syncthreads();
        s[tid] += t;
        __syncthreads();
    }
    g_bsum[tid] = s[tid] - v;                       // exclusive block offsets
}

__global__ void k_scan3(int E) {
    int gid = blockIdx.x * blockDim.x + threadIdx.x;
    if (gid < NN) {
        int rp = g_partial[gid] + g_bsum[gid >> 10];
        g_rowptr[gid] = rp;
        g_cursor[gid] = rp;
        g_dinv[gid] = rsqrtf((float)(g_cnt[gid] + 1));  // +1 self loop
    }
    if (gid == 0) g_rowptr[NN] = E;
}

__global__ void k_perm(const int* __restrict__ src, const int* __restrict__ dst, int E) {
    int i = blockIdx.x * blockDim.x + threadIdx.x;
    if (i < E) {
        int pos = atomicAdd(&g_cursor[dst[i]], 1);
        g_perm[pos] = src[i];
    }
}

// ---------------- GEMM1: g_hs = (x @ W0) * dinv ----------------
// Block = 128 threads: rg = tid>>2 (0..31), cg = tid&3.
// Thread computes 8 rows {rg + 32c} x 4 cols {cg + 4j}; tile = 256 rows.
// x tile stored row-rotated: xs[r*32 + ((k + r) & 31)]  -> conflict-free both ways.
// smem = 256*32*4 + 256*16*4 = 32768 + 16384 = 49152 B.
__global__ void __launch_bounds__(128) k_gemm1(const float* __restrict__ x,
                                               const float* __restrict__ W0) {
    __shared__ float xs[256 * 32];
    __shared__ float Ws[F_IN * CH];
    const int tid = threadIdx.x;
    const int rg  = tid >> 2;
    const int cg  = tid & 3;
    const int row0 = blockIdx.x * 256;

    // stage W0 (native [K][16] layout): 4096 floats = 1024 float4
    #pragma unroll
    for (int i = 0; i < 8; i++)
        ((float4*)Ws)[tid + 128 * i] = ((const float4*)W0)[tid + 128 * i];

    float acc[8][4];
    #pragma unroll
    for (int c = 0; c < 8; c++)
        #pragma unroll
        for (int j = 0; j < 4; j++) acc[c][j] = 0.f;

    for (int kc = 0; kc < F_IN; kc += 32) {
        __syncthreads();
        // stage 256 rows x 32 k: 2048 float4 loads, 16 per thread, coalesced
        #pragma unroll
        for (int it = 0; it < 16; it++) {
            int f = tid + 128 * it;
            int r = f >> 3;
            int q = f & 7;
            int grow = row0 + r;
            float4 v = make_float4(0.f, 0.f, 0.f, 0.f);
            if (grow < NN) v = *(const float4*)(x + (size_t)grow * F_IN + kc + 4 * q);
            int b = r * 32;
            xs[b + ((4 * q + 0 + r) & 31)] = v.x;
            xs[b + ((4 * q + 1 + r) & 31)] = v.y;
            xs[b + ((4 * q + 2 + r) & 31)] = v.z;
            xs[b + ((4 * q + 3 + r) & 31)] = v.w;
        }
        __syncthreads();

        #pragma unroll 8
        for (int kl = 0; kl < 32; kl++) {
            int col = (kl + rg) & 31;
            const float* wrow = Ws + (kc + kl) * CH + cg;
            float w0 = wrow[0];
            float w1 = wrow[4];
            float w2 = wrow[8];
            float w3 = wrow[12];
            #pragma unroll
            for (int c = 0; c < 8; c++) {
                float xv = xs[(rg + 32 * c) * 32 + col];
                acc[c][0] += xv * w0;
                acc[c][1] += xv * w1;
                acc[c][2] += xv * w2;
                acc[c][3] += xv * w3;
            }
        }
    }

    #pragma unroll
    for (int c = 0; c < 8; c++) {
        int grow = row0 + rg + 32 * c;
        if (grow < NN) {
            float di = g_dinv[grow];
            float* o = g_hs + (size_t)grow * CH + cg;
            o[0]  = acc[c][0] * di;
            o[4]  = acc[c][1] * di;
            o[8]  = acc[c][2] * di;
            o[12] = acc[c][3] * di;
        }
    }
}

// ---------------- aggregation layer 1 (gather, warp per node) ----------------
// out1[d] = dinv[d] * ( sum_{s->d} hs[s] + hs[d] )
__global__ void __launch_bounds__(256) k_agg1() {
    int warp = (blockIdx.x * blockDim.x + threadIdx.x) >> 5;
    if (warp >= NN) return;
    int lane = threadIdx.x & 31;
    int d = warp;
    int base = g_rowptr[d];
    int end  = g_rowptr[d + 1];
    int qc = lane & 3;      // column quad (16B)
    int ei = lane >> 2;     // edge slot (8 edges per iter)

    float4 acc = make_float4(0.f, 0.f, 0.f, 0.f);
    const float4* hs4 = (const float4*)g_hs;
    for (int i = base + ei; i < end; i += 8) {
        int s = g_perm[i];
        float4 v = hs4[(size_t)s * 4 + qc];
        acc.x += v.x; acc.y += v.y; acc.z += v.z; acc.w += v.w;
    }
    #pragma unroll
    for (int off = 4; off < 32; off <<= 1) {
        acc.x += __shfl_xor_sync(0xffffffffu, acc.x, off);
        acc.y += __shfl_xor_sync(0xffffffffu, acc.y, off);
        acc.z += __shfl_xor_sync(0xffffffffu, acc.z, off);
        acc.w += __shfl_xor_sync(0xffffffffu, acc.w, off);
    }
    if (lane < 4) {
        float4 self = hs4[(size_t)d * 4 + lane];
        float di = g_dinv[d];
        float4 r;
        r.x = (acc.x + self.x) * di;
        r.y = (acc.y + self.y) * di;
        r.z = (acc.z + self.z) * di;
        r.w = (acc.w + self.w) * di;
        ((float4*)g_out1)[(size_t)d * 4 + lane] = r;
    }
}

// ---------------- mid: hs2 = (relu(out1) @ W1) * dinv (padded to 8 cols) ------
__global__ void __launch_bounds__(256) k_mid(const float* __restrict__ W1) {
    __shared__ float W1s[CH * NL];
    if (threadIdx.x < CH * NL) W1s[threadIdx.x] = W1[threadIdx.x];
    __syncthreads();

    int row = blockIdx.x * blockDim.x + threadIdx.x;
    if (row >= NN) return;

    float h[CH];
    const float4* o4 = (const float4*)(g_out1 + (size_t)row * CH);
    #pragma unroll
    for (int q = 0; q < 4; q++) {
        float4 v = o4[q];
        h[q * 4 + 0] = fmaxf(v.x, 0.f);
        h[q * 4 + 1] = fmaxf(v.y, 0.f);
        h[q * 4 + 2] = fmaxf(v.z, 0.f);
        h[q * 4 + 3] = fmaxf(v.w, 0.f);
    }
    float acc[NL];
    #pragma unroll
    for (int j = 0; j < NL; j++) acc[j] = 0.f;
    #pragma unroll
    for (int k = 0; k < CH; k++) {
        float hv = h[k];
        #pragma unroll
        for (int j = 0; j < NL; j++) acc[j] += hv * W1s[k * NL + j];
    }
    float di = g_dinv[row];
    float4 lo = make_float4(acc[0] * di, acc[1] * di, acc[2] * di, acc[3] * di);
    float4 hi = make_float4(acc[4] * di, acc[5] * di, acc[6] * di, 0.f);
    float4* d4 = (float4*)(g_hs2 + (size_t)row * CH2);
    d4[0] = lo;
    d4[1] = hi;
}

// ---------------- aggregation layer 2 + fused exp epilogue ----------------
__global__ void __launch_bounds__(256) k_agg2(float* __restrict__ out) {
    int warp = (blockIdx.x * blockDim.x + threadIdx.x) >> 5;
    if (warp >= NN) return;
    int lane = threadIdx.x & 31;
    int d = warp;
    int base = g_rowptr[d];
    int end  = g_rowptr[d + 1];
    int qc = lane & 1;      // column quad
    int ei = lane >> 1;     // edge slot (16 edges per iter)

    float4 acc = make_float4(0.f, 0.f, 0.f, 0.f);
    const float4* hs4 = (const float4*)g_hs2;
    for (int i = base + ei; i < end; i += 16) {
        int s = g_perm[i];
        float4 v = hs4[(size_t)s * 2 + qc];
        acc.x += v.x; acc.y += v.y; acc.z += v.z; acc.w += v.w;
    }
    #pragma unroll
    for (int off = 2; off < 32; off <<= 1) {
        acc.x += __shfl_xor_sync(0xffffffffu, acc.x, off);
        acc.y += __shfl_xor_sync(0xffffffffu, acc.y, off);
        acc.z += __shfl_xor_sync(0xffffffffu, acc.z, off);
        acc.w += __shfl_xor_sync(0xffffffffu, acc.w, off);
    }
    if (lane < 2) {
        float4 self = hs4[(size_t)d * 2 + lane];
        float di = g_dinv[d];
        float r0 = expf((acc.x + self.x) * di) + 1.0f;
        float r1 = expf((acc.y + self.y) * di) + 1.0f;
        float r2 = expf((acc.z + self.z) * di) + 1.0f;
        float r3 = expf((acc.w + self.w) * di) + 1.0f;
        float* o = out + (size_t)d * NL + lane * 4;
        o[0] = r0;
        o[1] = r1;
        o[2] = r2;
        if (lane == 0) o[3] = r3;   // lane 1 covers cols 4..6 only
    }
}

// ---------------- launch ----------------
extern "C" void kernel_launch(void* const* d_in, const int* in_sizes, int n_in,
                              void* d_out, int out_size) {
    const float* x  = (const float*)d_in[0];
    const float* W0 = (const float*)d_in[1];
    const float* W1 = (const float*)d_in[2];
    const int*   ei = (const int*)d_in[3];
    const int E = in_sizes[3] / 2;
    const int* src = ei;
    const int* dst = ei + E;
    float* out = (float*)d_out;

    const int NB = (NN + 1023) / 1024;   // 98

    k_zero <<<(NN + 255) / 256, 256>>>();
    k_count<<<(E + 255) / 256, 256>>>(dst, E);
    k_scan1<<<NB, 1024>>>();
    k_scan2<<<1, 1024>>>(NB);
    k_scan3<<<(NN + 255) / 256, 256>>>(E);
    k_perm <<<(E + 255) / 256, 256>>>(src, dst, E);

    k_gemm1<<<(NN + 255) / 256, 128>>>(x, W0);

    k_agg1<<<(NN * 32 + 255) / 256, 256>>>();
    k_mid <<<(NN + 255) / 256, 256>>>(W1);
    k_agg2<<<(NN * 32 + 255) / 256, 256>>>(out);
}

// round 4
// speedup vs baseline: 1.5052x; 1.5052x over previous
#include <cuda_runtime.h>

#define NN 100000
#define F_IN 256
#define CH 16
#define CH2 8
#define NL 7

// ---------------- scratch (static device memory; no allocs) ----------------
__device__ __align__(128) float g_hs  [NN * CH];   // layer1 pre-scaled transform
__device__ __align__(128) float g_out1[NN * CH];   // layer1 accumulator
__device__ __align__(128) float g_hs2 [NN * CH2];  // layer2 pre-scaled transform (padded)
__device__ __align__(128) float g_out2[NN * CH2];  // layer2 accumulator (padded)
__device__ float g_dinv[NN];
__device__ int   g_deg [NN];

// vector float4 reduction (no return): red.global.add.v4.f32
__device__ __forceinline__ void red_add_f32x4(float* p, float a, float b, float c, float d) {
    asm volatile("red.global.add.v4.f32 [%0], {%1, %2, %3, %4};"
                 :: "l"(p), "f"(a), "f"(b), "f"(c), "f"(d) : "memory");
}

// packed dual fp32 FMA (sm_100a+): d.lo += a.lo*b.lo ; d.hi += a.hi*b.hi
__device__ __forceinline__ void ffma2(unsigned long long& d,
                                      unsigned long long a,
                                      unsigned long long b) {
    asm("fma.rn.f32x2 %0, %1, %2, %0;" : "+l"(d) : "l"(a), "l"(b));
}
__device__ __forceinline__ float f32x2_sum(unsigned long long v) {
    float lo = __uint_as_float((unsigned int)(v & 0xffffffffull));
    float hi = __uint_as_float((unsigned int)(v >> 32));
    return lo + hi;
}

// ---------------- degree / norm ----------------
__global__ void k_init_deg() {
    int i = blockIdx.x * blockDim.x + threadIdx.x;
    if (i < NN) g_deg[i] = 1;   // self loop
}

__global__ void k_deg(const int* __restrict__ dst, int E) {
    int i = blockIdx.x * blockDim.x + threadIdx.x;
    if (i < E) atomicAdd(&g_deg[dst[i]], 1);
}

__global__ void k_dinv() {
    int i = blockIdx.x * blockDim.x + threadIdx.x;
    if (i < NN) g_dinv[i] = rsqrtf((float)g_deg[i]);
}

// ---------------- GEMM1: hs = (x @ W0) * dinv, also init out1 ----------------
// 128 threads; tile = 192 rows; k-chunk = 32.
// Thread (rg=tid>>2, cg=tid&3) computes rows {rg+32c, c=0..5} x cols {cg+4j, j=0..3}.
// xs: row-major, stride 36 floats (pad) -> LDS.64 over k-pairs, conflict-free.
// Ws: W0 transposed [16][256], stride 258 -> LDS.64 over k-pairs, conflict-free.
// Packed accumulators: lo-half = even-k partial, hi-half = odd-k partial.
#define TR 192
#define KCH 32
__global__ void __launch_bounds__(128) k_gemm1(const float* __restrict__ x,
                                               const float* __restrict__ W0) {
    __shared__ float xs[TR * 36];        // 27648 B
    __shared__ float Ws[CH * 258];       // 16512 B
    const int tid = threadIdx.x;
    const int rg  = tid >> 2;
    const int cg  = tid & 3;
    const int row0 = blockIdx.x * TR;

    // stage W0 transposed: 4096 elems, 32 per thread (coalesced read)
    #pragma unroll
    for (int i = 0; i < 32; i++) {
        int idx = tid + 128 * i;
        int k = idx >> 4;
        int j = idx & 15;
        Ws[j * 258 + k] = W0[idx];
    }

    unsigned long long acc[6][4];
    #pragma unroll
    for (int c = 0; c < 6; c++)
        #pragma unroll
        for (int j = 0; j < 4; j++) acc[c][j] = 0ull;

    for (int kc = 0; kc < F_IN; kc += KCH) {
        __syncthreads();
        // stage 192 rows x 32 k: 1536 float4, 12 per thread, coalesced
        #pragma unroll
        for (int it = 0; it < 12; it++) {
            int f = tid + 128 * it;
            int r = f >> 3;
            int q = f & 7;
            int grow = row0 + r;
            float4 v = make_float4(0.f, 0.f, 0.f, 0.f);
            if (grow < NN) v = *(const float4*)(x + (size_t)grow * F_IN + kc + 4 * q);
            *(float4*)(xs + r * 36 + 4 * q) = v;
        }
        __syncthreads();

        #pragma unroll 4
        for (int kp = 0; kp < KCH / 2; kp++) {
            unsigned long long w2[4];
            #pragma unroll
            for (int j = 0; j < 4; j++)
                w2[j] = *(const unsigned long long*)(Ws + (cg + 4 * j) * 258 + kc + 2 * kp);
            #pragma unroll
            for (int c = 0; c < 6; c++) {
                unsigned long long xv =
                    *(const unsigned long long*)(xs + (rg + 32 * c) * 36 + 2 * kp);
                ffma2(acc[c][0], xv, w2[0]);
                ffma2(acc[c][1], xv, w2[1]);
                ffma2(acc[c][2], xv, w2[2]);
                ffma2(acc[c][3], xv, w2[3]);
            }
        }
    }

    #pragma unroll
    for (int c = 0; c < 6; c++) {
        int grow = row0 + rg + 32 * c;
        if (grow < NN) {
            float di = g_dinv[grow];
            float* o1 = g_hs  + (size_t)grow * CH + cg;
            float* o2 = g_out1 + (size_t)grow * CH + cg;
            #pragma unroll
            for (int j = 0; j < 4; j++) {
                float v = f32x2_sum(acc[c][j]) * di;
                o1[4 * j] = v;
                o2[4 * j] = v;   // self-loop contribution
            }
        }
    }
}

// ---------------- edge scatter, layer 1 (16 floats/row, 4 threads/edge) ----------------
__global__ void k_edge1(const int* __restrict__ src, const int* __restrict__ dst, int E) {
    int t = blockIdx.x * blockDim.x + threadIdx.x;
    if (t >= 4 * E) return;
    int e = t >> 2;
    int c = t & 3;
    int s = src[e];
    int d = dst[e];
    float4 v = ((const float4*)(g_hs + (size_t)s * CH))[c];
    red_add_f32x4((float*)(((float4*)(g_out1 + (size_t)d * CH)) + c), v.x, v.y, v.z, v.w);
}

// ---------------- mid: h1 = relu(out1*dinv); hs2 = (h1 @ W1)*dinv; init out2 ----------
__global__ void __launch_bounds__(256) k_mid(const float* __restrict__ W1) {
    __shared__ float W1s[CH * NL];
    if (threadIdx.x < CH * NL) W1s[threadIdx.x] = W1[threadIdx.x];
    __syncthreads();

    int t = blockIdx.x * blockDim.x + threadIdx.x;
    int row0 = t * 4;
    if (row0 >= NN) return;   // NN divisible by 4

    float h[4][CH];
    float di[4];
    #pragma unroll
    for (int r = 0; r < 4; r++) {
        int row = row0 + r;
        di[r] = g_dinv[row];
        #pragma unroll
        for (int q = 0; q < 4; q++) {
            float4 v = *(const float4*)(g_out1 + (size_t)row * CH + q * 4);
            h[r][q * 4 + 0] = fmaxf(v.x * di[r], 0.f);
            h[r][q * 4 + 1] = fmaxf(v.y * di[r], 0.f);
            h[r][q * 4 + 2] = fmaxf(v.z * di[r], 0.f);
            h[r][q * 4 + 3] = fmaxf(v.w * di[r], 0.f);
        }
    }

    float acc[4][NL];
    #pragma unroll
    for (int r = 0; r < 4; r++)
        #pragma unroll
        for (int c = 0; c < NL; c++) acc[r][c] = 0.f;

    #pragma unroll
    for (int jj = 0; jj < CH; jj++) {
        #pragma unroll
        for (int c = 0; c < NL; c++) {
            float w = W1s[jj * NL + c];
            #pragma unroll
            for (int r = 0; r < 4; r++) acc[r][c] += h[r][jj] * w;
        }
    }

    #pragma unroll
    for (int r = 0; r < 4; r++) {
        int row = row0 + r;
        float4 lo = make_float4(acc[r][0] * di[r], acc[r][1] * di[r],
                                acc[r][2] * di[r], acc[r][3] * di[r]);
        float4 hi = make_float4(acc[r][4] * di[r], acc[r][5] * di[r],
                                acc[r][6] * di[r], 0.f);
        *(float4*)(g_hs2  + (size_t)row * CH2)     = lo;
        *(float4*)(g_hs2  + (size_t)row * CH2 + 4) = hi;
        *(float4*)(g_out2 + (size_t)row * CH2)     = lo;   // self loop
        *(float4*)(g_out2 + (size_t)row * CH2 + 4) = hi;
    }
}

// ---------------- edge scatter, layer 2 (8 floats/row padded, 2 threads/edge) ----------
__global__ void k_edge2(const int* __restrict__ src, const int* __restrict__ dst, int E) {
    int t = blockIdx.x * blockDim.x + threadIdx.x;
    if (t >= 2 * E) return;
    int e = t >> 1;
    int c = t & 1;
    int s = src[e];
    int d = dst[e];
    float4 v = ((const float4*)(g_hs2 + (size_t)s * CH2))[c];
    red_add_f32x4((float*)(((float4*)(g_out2 + (size_t)d * CH2)) + c), v.x, v.y, v.z, v.w);
}

// ---------------- finalize: out = exp(out2*dinv) + 1 ----------------
__global__ void k_final(float* __restrict__ out) {
    int t = blockIdx.x * blockDim.x + threadIdx.x;
    if (t >= NN * NL) return;
    int i = t / NL;
    int j = t - i * NL;
    out[t] = expf(g_out2[(size_t)i * CH2 + j] * g_dinv[i]) + 1.0f;
}

// ---------------- launch ----------------
extern "C" void kernel_launch(void* const* d_in, const int* in_sizes, int n_in,
                              void* d_out, int out_size) {
    const float* x  = (const float*)d_in[0];
    const float* W0 = (const float*)d_in[1];
    const float* W1 = (const float*)d_in[2];
    const int*   ei = (const int*)d_in[3];
    const int E = in_sizes[3] / 2;
    const int* src = ei;
    const int* dst = ei + E;
    float* out = (float*)d_out;

    k_init_deg<<<(NN + 255) / 256, 256>>>();
    k_deg<<<(E + 255) / 256, 256>>>(dst, E);
    k_dinv<<<(NN + 255) / 256, 256>>>();

    k_gemm1<<<(NN + TR - 1) / TR, 128>>>(x, W0);

    k_edge1<<<(4 * E + 255) / 256, 256>>>(src, dst, E);

    k_mid<<<(NN / 4 + 255) / 256, 256>>>(W1);

    k_edge2<<<(2 * E + 255) / 256, 256>>>(src, dst, E);

    k_final<<<(NN * NL + 255) / 256, 256>>>(out);
}